// round 15
// baseline (speedup 1.0000x reference)
#include <cuda_runtime.h>
#include <cuda_bf16.h>

// DotPredictor: out[e] = sigmoid(dot(h[src[e]], h[dst[e]])), D = 64 fp32.
// Indices are int32 (JAX x64 disabled).
// FINAL FORM: 8 lanes per group, 2 edges per group; 8 independent
// LDG.128/thread, each warp-level LDG covers full 128B lines
// (wavefront-optimal: 4 lines/edge = irreducible). Plain 6-shuffle
// reduction (32 regs -> ~85% occ; all reg-heavier variants measured
// slower). tanh.approx sigmoid. Even-E fast path: no tail selects,
// single float2 store. Kernel is at the L1tex-wavefront/L2 queueing
// plateau (~60% of both) — measured floor for this access pattern.

#define D 64

__device__ __forceinline__ float fast_sigmoid(float x)
{
    // sigmoid(x) = 0.5 * tanh(x/2) + 0.5 ; err ~2^-11 << 1e-3 budget
    float t;
    asm("tanh.approx.f32 %0, %1;" : "=f"(t) : "f"(x * 0.5f));
    return fmaf(t, 0.5f, 0.5f);
}

template <bool EVEN_E>
__global__ void __launch_bounds__(256) dotpred_kernel(
    const float* __restrict__ h,
    const int* __restrict__ src,
    const int* __restrict__ dst,
    float* __restrict__ out,
    int E)
{
    int gid   = blockIdx.x * blockDim.x + threadIdx.x;
    int group = gid >> 3;            // 8 lanes per group
    int lane  = gid & 7;
    int e0 = group * 2;
    if (e0 >= E) return;

    // Vectorized index loads: edge pair is 8B-aligned in src/dst
    int2 ss = reinterpret_cast<const int2*>(src)[group];
    int2 dd = reinterpret_cast<const int2*>(dst)[group];

    int s1i, d1i;
    if (EVEN_E) {
        s1i = ss.y;
        d1i = dd.y;
    } else {
        bool has_e1 = (e0 + 1 < E);
        s1i = has_e1 ? ss.y : ss.x;
        d1i = has_e1 ? dd.y : dd.x;
    }

    const float4* __restrict__ s0p =
        reinterpret_cast<const float4*>(h + (long long)ss.x * D);
    const float4* __restrict__ d0p =
        reinterpret_cast<const float4*>(h + (long long)dd.x * D);
    const float4* __restrict__ s1p =
        reinterpret_cast<const float4*>(h + (long long)s1i * D);
    const float4* __restrict__ d1p =
        reinterpret_cast<const float4*>(h + (long long)d1i * D);

    // 8 independent 16B loads; each warp-level LDG covers 4 full 128B lines
    float4 a0 = s0p[lane];
    float4 a1 = s0p[lane + 8];
    float4 b0 = d0p[lane];
    float4 b1 = d0p[lane + 8];
    float4 c0 = s1p[lane];
    float4 c1 = s1p[lane + 8];
    float4 f0 = d1p[lane];
    float4 f1 = d1p[lane + 8];

    float acc0 = a0.x * b0.x;
    float acc1 = c0.x * f0.x;
    acc0 = fmaf(a0.y, b0.y, acc0);
    acc1 = fmaf(c0.y, f0.y, acc1);
    acc0 = fmaf(a0.z, b0.z, acc0);
    acc1 = fmaf(c0.z, f0.z, acc1);
    acc0 = fmaf(a0.w, b0.w, acc0);
    acc1 = fmaf(c0.w, f0.w, acc1);
    acc0 = fmaf(a1.x, b1.x, acc0);
    acc1 = fmaf(c1.x, f1.x, acc1);
    acc0 = fmaf(a1.y, b1.y, acc0);
    acc1 = fmaf(c1.y, f1.y, acc1);
    acc0 = fmaf(a1.z, b1.z, acc0);
    acc1 = fmaf(c1.z, f1.z, acc1);
    acc0 = fmaf(a1.w, b1.w, acc0);
    acc1 = fmaf(c1.w, f1.w, acc1);

    // Reduce both accumulators across the 8-lane group
    acc0 += __shfl_xor_sync(0xFFFFFFFFu, acc0, 4);
    acc1 += __shfl_xor_sync(0xFFFFFFFFu, acc1, 4);
    acc0 += __shfl_xor_sync(0xFFFFFFFFu, acc0, 2);
    acc1 += __shfl_xor_sync(0xFFFFFFFFu, acc1, 2);
    acc0 += __shfl_xor_sync(0xFFFFFFFFu, acc0, 1);
    acc1 += __shfl_xor_sync(0xFFFFFFFFu, acc1, 1);

    if (lane == 0) {
        float r0 = fast_sigmoid(acc0);
        float r1 = fast_sigmoid(acc1);
        if (EVEN_E) {
            reinterpret_cast<float2*>(out)[group] = make_float2(r0, r1);
        } else {
            out[e0] = r0;
            if (e0 + 1 < E) out[e0 + 1] = r1;
        }
    }
}

extern "C" void kernel_launch(void* const* d_in, const int* in_sizes, int n_in,
                              void* d_out, int out_size)
{
    const float* h   = (const float*)d_in[0];
    const int*   src = (const int*)d_in[1];
    const int*   dst = (const int*)d_in[2];
    float*       out = (float*)d_out;

    int E = in_sizes[1];  // number of edges

    long long groups = ((long long)E + 1) / 2;
    long long total_threads = groups * 8;
    const int threads = 256;
    int blocks = (int)((total_threads + threads - 1) / threads);

    if ((E & 1) == 0) {
        dotpred_kernel<true><<<blocks, threads>>>(h, src, dst, out, E);
    } else {
        dotpred_kernel<false><<<blocks, threads>>>(h, src, dst, out, E);
    }
}

// round 16
// speedup vs baseline: 1.0090x; 1.0090x over previous
#include <cuda_runtime.h>
#include <cuda_bf16.h>

// DotPredictor: out[e] = sigmoid(dot(h[src[e]], h[dst[e]])), D = 64 fp32.
// Indices are int32 (JAX x64 disabled).
// FINAL (= R14, best measured binary: 32 regs, ~84% occ, L2 66%).
// 8 lanes per group, 2 edges per group; 8 independent LDG.128/thread,
// each warp-level LDG covers full 128B lines (wavefront-optimal:
// 4 lines/edge is irreducible traffic). Plain 6-shuffle reduction —
// every reg-heavier variant (wider MLP, prefetch, persistence,
// specialization) measured slower via occupancy loss. tanh.approx
// sigmoid (err ~2^-11 << 1e-3 budget).

#define D 64

__device__ __forceinline__ float fast_sigmoid(float x)
{
    // sigmoid(x) = 0.5 * tanh(x/2) + 0.5
    float t;
    asm("tanh.approx.f32 %0, %1;" : "=f"(t) : "f"(x * 0.5f));
    return fmaf(t, 0.5f, 0.5f);
}

__global__ void __launch_bounds__(256) dotpred_kernel(
    const float* __restrict__ h,
    const int* __restrict__ src,
    const int* __restrict__ dst,
    float* __restrict__ out,
    int E)
{
    int gid   = blockIdx.x * blockDim.x + threadIdx.x;
    int group = gid >> 3;            // 8 lanes per group
    int lane  = gid & 7;
    int e0 = group * 2;
    int e1 = e0 + 1;
    if (e0 >= E) return;
    bool has_e1 = (e1 < E);

    // Vectorized index loads: edge pair is 8B-aligned in src/dst
    int2 ss = reinterpret_cast<const int2*>(src)[group];
    int2 dd = reinterpret_cast<const int2*>(dst)[group];

    const float4* __restrict__ s0p =
        reinterpret_cast<const float4*>(h + (long long)ss.x * D);
    const float4* __restrict__ d0p =
        reinterpret_cast<const float4*>(h + (long long)dd.x * D);
    const float4* __restrict__ s1p =
        reinterpret_cast<const float4*>(h + (long long)(has_e1 ? ss.y : ss.x) * D);
    const float4* __restrict__ d1p =
        reinterpret_cast<const float4*>(h + (long long)(has_e1 ? dd.y : dd.x) * D);

    // 8 independent 16B loads; each warp-level LDG covers 4 full 128B lines
    float4 a0 = s0p[lane];
    float4 a1 = s0p[lane + 8];
    float4 b0 = d0p[lane];
    float4 b1 = d0p[lane + 8];
    float4 c0 = s1p[lane];
    float4 c1 = s1p[lane + 8];
    float4 f0 = d1p[lane];
    float4 f1 = d1p[lane + 8];

    float acc0 = a0.x * b0.x;
    float acc1 = c0.x * f0.x;
    acc0 = fmaf(a0.y, b0.y, acc0);
    acc1 = fmaf(c0.y, f0.y, acc1);
    acc0 = fmaf(a0.z, b0.z, acc0);
    acc1 = fmaf(c0.z, f0.z, acc1);
    acc0 = fmaf(a0.w, b0.w, acc0);
    acc1 = fmaf(c0.w, f0.w, acc1);
    acc0 = fmaf(a1.x, b1.x, acc0);
    acc1 = fmaf(c1.x, f1.x, acc1);
    acc0 = fmaf(a1.y, b1.y, acc0);
    acc1 = fmaf(c1.y, f1.y, acc1);
    acc0 = fmaf(a1.z, b1.z, acc0);
    acc1 = fmaf(c1.z, f1.z, acc1);
    acc0 = fmaf(a1.w, b1.w, acc0);
    acc1 = fmaf(c1.w, f1.w, acc1);

    // Reduce both accumulators across the 8-lane group
    acc0 += __shfl_xor_sync(0xFFFFFFFFu, acc0, 4);
    acc1 += __shfl_xor_sync(0xFFFFFFFFu, acc1, 4);
    acc0 += __shfl_xor_sync(0xFFFFFFFFu, acc0, 2);
    acc1 += __shfl_xor_sync(0xFFFFFFFFu, acc1, 2);
    acc0 += __shfl_xor_sync(0xFFFFFFFFu, acc0, 1);
    acc1 += __shfl_xor_sync(0xFFFFFFFFu, acc1, 1);

    if (lane == 0) {
        out[e0] = fast_sigmoid(acc0);
        if (has_e1)
            out[e1] = fast_sigmoid(acc1);
    }
}

extern "C" void kernel_launch(void* const* d_in, const int* in_sizes, int n_in,
                              void* d_out, int out_size)
{
    const float* h   = (const float*)d_in[0];
    const int*   src = (const int*)d_in[1];
    const int*   dst = (const int*)d_in[2];
    float*       out = (float*)d_out;

    int E = in_sizes[1];  // number of edges

    long long groups = ((long long)E + 1) / 2;
    long long total_threads = groups * 8;
    const int threads = 256;
    int blocks = (int)((total_threads + threads - 1) / threads);

    dotpred_kernel<<<blocks, threads>>>(h, src, dst, out, E);
}